// round 1
// baseline (speedup 1.0000x reference)
#include <cuda_runtime.h>
#include <cuda_bf16.h>
#include <mma.h>

using namespace nvcuda;

// Problem constants
constexpr int BATCH = 8192;
constexpr int DH    = 1024;   // hidden size (per gate)
constexpr int KTOT  = 2048;   // concat K: [x | h]
constexpr int KHALF = 1024;

// Tiling
constexpr int BM = 128;       // batch rows per CTA
constexpr int BN = 64;        // hidden-j cols per CTA (per gate; CTA does all 4 gates)
constexpr int BK = 32;        // K step
constexpr int THREADS = 512;  // 16 warps

// Shared layout (floats)
constexpr int LDA = 40;                 // padded BK
constexpr int LDB = 40;
constexpr int LDC = 72;                 // padded BN for epilogue tiles
constexpr int A_FLOATS   = BM * LDA;            // 5120
constexpr int B_FLOATS   = 4 * BN * LDB;        // 10240
constexpr int EPI_FLOATS = 4 * 64 * LDC;        // 18432  (two row-halves of BM)
constexpr int SMEM_BYTES = EPI_FLOATS * 4;      // 73728 (> stage 61440)

struct Params {
    const float* x;     // [B, 1024]
    const float* h;     // [B, 1024]
    const float* c;     // [B, 1024]
    const float* W[4];  // Wi,Wf,Wo,Wc  [1024, 1024]
    const float* U[4];  // Ui,Uf,Uo,Uc  [1024, 1024]
    const float* bias[4];
    float* outh;        // [B, 1024]
    float* outc;        // [B, 1024]
};

__device__ __forceinline__ float sigmoidf_(float v) {
    return 1.0f / (1.0f + __expf(-v));
}

__global__ void __launch_bounds__(THREADS, 1)
lstm_fused_tf32_kernel(Params p)
{
    extern __shared__ float sm[];
    float* As = sm;                 // [BM][LDA]
    float* Bs = sm + A_FLOATS;      // [4][BN][LDB]

    const int tid = threadIdx.x;
    const int w   = tid >> 5;
    const int wm  = w & 7;          // row tile (0..7): rows wm*16
    const int wn  = w >> 3;         // col pair (0..1): col tiles wn*2, wn*2+1

    const int bm = blockIdx.y * BM;   // batch base
    const int j0 = blockIdx.x * BN;   // hidden-j base

    wmma::fragment<wmma::accumulator, 16, 16, 8, float> acc[4][2];
    #pragma unroll
    for (int g = 0; g < 4; g++)
        #pragma unroll
        for (int ci = 0; ci < 2; ci++)
            wmma::fill_fragment(acc[g][ci], 0.0f);

    const int KITERS = KTOT / BK;   // 64
    for (int kt = 0; kt < KITERS; kt++) {
        const int kbase = kt * BK;
        const bool xpart = (kbase < KHALF);
        const int klocal = xpart ? kbase : (kbase - KHALF);

        // ---- stage A tile: BM x BK  (1024 float4, 2 per thread) ----
        const float* aSrc = (xpart ? p.x : p.h) + klocal;
        #pragma unroll
        for (int t = tid; t < BM * (BK / 4); t += THREADS) {
            const int row = t >> 3;
            const int c4  = t & 7;
            const float4 v = *(const float4*)(aSrc + (size_t)(bm + row) * 1024 + c4 * 4);
            *(float4*)(As + row * LDA + c4 * 4) = v;
        }
        // ---- stage B tiles: 4 gates x BN x BK (2048 float4, 4 per thread) ----
        #pragma unroll
        for (int t = tid; t < 4 * BN * (BK / 4); t += THREADS) {
            const int g   = t >> 9;
            const int rem = t & 511;
            const int n   = rem >> 3;
            const int c4  = rem & 7;
            const float* bSrc = (xpart ? p.W[g] : p.U[g]) + klocal;
            const float4 v = *(const float4*)(bSrc + (size_t)(j0 + n) * 1024 + c4 * 4);
            *(float4*)(Bs + g * (BN * LDB) + n * LDB + c4 * 4) = v;
        }
        __syncthreads();

        // ---- MMA: 4 k-steps of k=8 ----
        #pragma unroll
        for (int kk = 0; kk < 4; kk++) {
            wmma::fragment<wmma::matrix_a, 16, 16, 8, wmma::precision::tf32, wmma::row_major> a_frag;
            wmma::load_matrix_sync(a_frag, &As[wm * 16 * LDA + kk * 8], LDA);
            #pragma unroll
            for (int t = 0; t < a_frag.num_elements; t++)
                a_frag.x[t] = wmma::__float_to_tf32(a_frag.x[t]);

            #pragma unroll
            for (int g = 0; g < 4; g++) {
                #pragma unroll
                for (int ci = 0; ci < 2; ci++) {
                    wmma::fragment<wmma::matrix_b, 16, 16, 8, wmma::precision::tf32, wmma::col_major> b_frag;
                    const int n0 = (wn * 2 + ci) * 16;
                    wmma::load_matrix_sync(b_frag, &Bs[g * (BN * LDB) + n0 * LDB + kk * 8], LDB);
                    #pragma unroll
                    for (int t = 0; t < b_frag.num_elements; t++)
                        b_frag.x[t] = wmma::__float_to_tf32(b_frag.x[t]);
                    wmma::mma_sync(acc[g][ci], a_frag, b_frag, acc[g][ci]);
                }
            }
        }
        __syncthreads();
    }

    // ---- fused epilogue: two row-halves of 64, gates stay in SMEM ----
    float* Cs = sm;  // [4][64][LDC]
    #pragma unroll
    for (int ph = 0; ph < 2; ph++) {
        if ((wm >> 2) == ph) {
            #pragma unroll
            for (int g = 0; g < 4; g++)
                #pragma unroll
                for (int ci = 0; ci < 2; ci++)
                    wmma::store_matrix_sync(
                        &Cs[g * (64 * LDC) + (wm & 3) * 16 * LDC + (wn * 2 + ci) * 16],
                        acc[g][ci], LDC, wmma::mem_row_major);
        }
        __syncthreads();

        for (int e = tid; e < 64 * BN; e += THREADS) {
            const int ml = e >> 6;
            const int n  = e & 63;
            const int row = bm + ph * 64 + ml;
            const int j   = j0 + n;

            const float gi = Cs[0 * (64 * LDC) + ml * LDC + n] + __ldg(&p.bias[0][j]);
            const float gf = Cs[1 * (64 * LDC) + ml * LDC + n] + __ldg(&p.bias[1][j]);
            const float go = Cs[2 * (64 * LDC) + ml * LDC + n] + __ldg(&p.bias[2][j]);
            const float gc = Cs[3 * (64 * LDC) + ml * LDC + n] + __ldg(&p.bias[3][j]);

            const float iv = sigmoidf_(gi);
            const float fv = sigmoidf_(gf);
            const float ov = sigmoidf_(go);
            const float cv = tanhf(gc);

            const float cold = __ldg(&p.c[(size_t)row * 1024 + j]);
            const float nc = fv * cold + iv * cv;
            const float nh = ov * tanhf(nc);

            p.outh[(size_t)row * 1024 + j] = nh;
            p.outc[(size_t)row * 1024 + j] = nc;
        }
        __syncthreads();
    }
}

extern "C" void kernel_launch(void* const* d_in, const int* in_sizes, int n_in,
                              void* d_out, int out_size)
{
    (void)in_sizes; (void)n_in;

    Params p;
    p.x = (const float*)d_in[0];
    p.h = (const float*)d_in[1];
    p.c = (const float*)d_in[2];
    // order: (Wi,bi,Ui), (Wf,bf,Uf), (Wo,bo,Uo), (Wc,bc,Uc)
    for (int g = 0; g < 4; g++) {
        p.W[g]    = (const float*)d_in[3 + 3 * g];
        p.bias[g] = (const float*)d_in[4 + 3 * g];
        p.U[g]    = (const float*)d_in[5 + 3 * g];
    }
    float* out = (float*)d_out;
    p.outh = out;                              // new_h first
    p.outc = out + (size_t)BATCH * DH;         // then new_c
    (void)out_size;

    cudaFuncSetAttribute(lstm_fused_tf32_kernel,
                         cudaFuncAttributeMaxDynamicSharedMemorySize, SMEM_BYTES);

    dim3 grid(DH / BN, BATCH / BM);  // (16, 64)
    lstm_fused_tf32_kernel<<<grid, THREADS, SMEM_BYTES>>>(p);
}

// round 3
// speedup vs baseline: 2.8914x; 2.8914x over previous
#include <cuda_runtime.h>
#include <cstdint>

// ---------------- problem constants ----------------
constexpr int BATCH = 8192;
constexpr int DH    = 1024;

// ---------------- tiling ----------------
constexpr int BM      = 128;   // batch rows per CTA
constexpr int BNG     = 64;    // cols per gate per CTA
constexpr int NTOT    = 256;   // 4 gates x 64
constexpr int BK      = 32;    // K per chunk
constexpr int KITERS  = 64;    // 2048 / 32
constexpr int NSTAGES = 4;
constexpr int THREADS = 512;   // 16 warps: 4(M) x 4(N)

constexpr int LDA = 36;                       // padded floats per A row
constexpr int LDB = 36;
constexpr int A_STAGE = BM * LDA;             // 4608 floats
constexpr int B_STAGE = NTOT * LDB;           // 9216 floats
constexpr int STAGE_FLOATS = A_STAGE + B_STAGE;          // 13824
constexpr int SMEM_BYTES   = NSTAGES * STAGE_FLOATS * 4; // 221184

struct Params {
    const float* x;     // [8192,1024]
    const float* h;
    const float* c;
    const float* W[4];  // [1024,1024]
    const float* U[4];
    const float* bias[4];
    float* outh;
    float* outc;
};

// ---------------- helpers ----------------
__device__ __forceinline__ uint32_t smem_u32(const void* p) {
    uint32_t a;
    asm("{ .reg .u64 t; cvta.to.shared.u64 t, %1; cvt.u32.u64 %0, t; }" : "=r"(a) : "l"(p));
    return a;
}
__device__ __forceinline__ void cp_async16(uint32_t dst, const void* src) {
    asm volatile("cp.async.cg.shared.global [%0], [%1], 16;" :: "r"(dst), "l"(src));
}
__device__ __forceinline__ void cp_commit() { asm volatile("cp.async.commit_group;"); }
template <int N> __device__ __forceinline__ void cp_wait() {
    asm volatile("cp.async.wait_group %0;" :: "n"(N));
}
__device__ __forceinline__ void mma_tf32(float* d, const uint32_t* a, const uint32_t* b) {
    asm volatile(
        "mma.sync.aligned.m16n8k8.row.col.f32.tf32.tf32.f32 "
        "{%0,%1,%2,%3}, {%4,%5,%6,%7}, {%8,%9}, {%0,%1,%2,%3};"
        : "+f"(d[0]), "+f"(d[1]), "+f"(d[2]), "+f"(d[3])
        : "r"(a[0]), "r"(a[1]), "r"(a[2]), "r"(a[3]), "r"(b[0]), "r"(b[1]));
}
__device__ __forceinline__ float sigm(float v) { return 1.0f / (1.0f + __expf(-v)); }
__device__ __forceinline__ uint32_t fbits(float v) { return __float_as_uint(v); }

// ---------------- kernel ----------------
__global__ void __launch_bounds__(THREADS, 1)
lstm_mma_tf32_kernel(Params p)
{
    extern __shared__ __align__(16) float sm[];
    const uint32_t sbase = smem_u32(sm);

    const int tid  = threadIdx.x;
    const int wid  = tid >> 5;
    const int lane = tid & 31;
    const int wm   = wid >> 2;        // 0..3 : M range wm*32
    const int wn   = wid & 3;         // 0..3 : j range wn*16 within each gate
    const int g4   = lane >> 2;       // 0..7
    const int t4   = lane & 3;        // 0..3

    const int bm = blockIdx.y * BM;
    const int j0 = blockIdx.x * BNG;

    // ---- per-thread staging assignments (fixed across chunks) ----
    // A: 1024 float4 tiles -> 2 per thread; B: 2048 -> 4 per thread
    uint32_t a_dst[2]; const float* a_src[2];
    #pragma unroll
    for (int i = 0; i < 2; i++) {
        const int idx = tid + i * THREADS;
        const int r = idx >> 3, c = idx & 7;
        a_dst[i] = sbase + (uint32_t)(r * LDA + c * 4) * 4u;
        a_src[i] = p.x + (size_t)(bm + r) * 1024 + c * 4;
    }
    uint32_t b_dst[4]; const float* b_src[4];
    #pragma unroll
    for (int i = 0; i < 4; i++) {
        const int idx = tid + i * THREADS;
        const int r = idx >> 3, c = idx & 7;     // r in [0,256)
        const int g = r >> 6, jl = r & 63;
        b_dst[i] = sbase + (uint32_t)((A_STAGE + r * LDB + c * 4)) * 4u;
        b_src[i] = p.W[g] + (size_t)(j0 + jl) * 1024 + c * 4;
    }

    auto stage = [&](int kn) {
        if (kn == 32) {  // switch x->h, W->U (recompute from param space)
            #pragma unroll
            for (int i = 0; i < 2; i++) {
                const int idx = tid + i * THREADS;
                const int r = idx >> 3, c = idx & 7;
                a_src[i] = p.h + (size_t)(bm + r) * 1024 + c * 4;
            }
            #pragma unroll
            for (int i = 0; i < 4; i++) {
                const int idx = tid + i * THREADS;
                const int r = idx >> 3, c = idx & 7;
                const int g = r >> 6, jl = r & 63;
                b_src[i] = p.U[g] + (size_t)(j0 + jl) * 1024 + c * 4;
            }
        }
        const int koff = (kn & 31) * BK;                    // float offset
        const uint32_t soff = (uint32_t)(kn & 3) * (STAGE_FLOATS * 4);
        #pragma unroll
        for (int i = 0; i < 2; i++) cp_async16(a_dst[i] + soff, a_src[i] + koff);
        #pragma unroll
        for (int i = 0; i < 4; i++) cp_async16(b_dst[i] + soff, b_src[i] + koff);
    };

    // ---- accumulators: [mtile][gate][n8-sub][4] ----
    float acc[2][4][2][4];
    #pragma unroll
    for (int a = 0; a < 2; a++)
        #pragma unroll
        for (int b = 0; b < 4; b++)
            #pragma unroll
            for (int s = 0; s < 2; s++)
                #pragma unroll
                for (int q = 0; q < 4; q++) acc[a][b][s][q] = 0.0f;

    // ---- prologue: stage chunks 0..2 ----
    #pragma unroll
    for (int kn = 0; kn < NSTAGES - 1; kn++) { stage(kn); cp_commit(); }

    // ---- main loop ----
    for (int kt = 0; kt < KITERS; kt++) {
        cp_wait<2>();
        __syncthreads();

        // issue loads for chunk kt+3 (slot (kt-1)%4, freed by the barrier)
        if (kt + NSTAGES - 1 < KITERS) stage(kt + NSTAGES - 1);
        cp_commit();   // empty group near the tail keeps wait<2> uniform

        const float* As = sm + (kt & 3) * STAGE_FLOATS;
        const float* Bs = As + A_STAGE;

        #pragma unroll
        for (int kk = 0; kk < 4; kk++) {
            const int k0 = kk * 8;
            uint32_t afr[2][4];
            #pragma unroll
            for (int mt = 0; mt < 2; mt++) {
                const float* ap = As + (wm * 32 + mt * 16 + g4) * LDA + k0 + t4;
                afr[mt][0] = fbits(ap[0]);
                afr[mt][1] = fbits(ap[8 * LDA]);
                afr[mt][2] = fbits(ap[4]);
                afr[mt][3] = fbits(ap[8 * LDA + 4]);
            }
            uint32_t bfr[4][2][2];
            #pragma unroll
            for (int g = 0; g < 4; g++)
                #pragma unroll
                for (int s2 = 0; s2 < 2; s2++) {
                    const int n0 = g * 64 + wn * 16 + s2 * 8;
                    const float* bp = Bs + (n0 + g4) * LDB + k0 + t4;
                    bfr[g][s2][0] = fbits(bp[0]);
                    bfr[g][s2][1] = fbits(bp[4]);
                }
            #pragma unroll
            for (int mt = 0; mt < 2; mt++)
                #pragma unroll
                for (int g = 0; g < 4; g++)
                    #pragma unroll
                    for (int s2 = 0; s2 < 2; s2++)
                        mma_tf32(acc[mt][g][s2], afr[mt], bfr[g][s2]);
        }
    }

    // ---- fused epilogue (register-resident; float2 I/O) ----
    {
        float2 bb[4][2];
        #pragma unroll
        for (int g = 0; g < 4; g++)
            #pragma unroll
            for (int s2 = 0; s2 < 2; s2++)
                bb[g][s2] = *(const float2*)(p.bias[g] + j0 + wn * 16 + s2 * 8 + 2 * t4);

        #pragma unroll
        for (int mt = 0; mt < 2; mt++) {
            #pragma unroll
            for (int hh = 0; hh < 2; hh++) {
                const int row = bm + wm * 32 + mt * 16 + g4 + hh * 8;
                const size_t ro = (size_t)row * 1024 + j0 + wn * 16;
                #pragma unroll
                for (int s2 = 0; s2 < 2; s2++) {
                    const int co = s2 * 8 + 2 * t4;
                    const float2 cv = *(const float2*)(p.c + ro + co);
                    const int q = hh * 2;

                    const float i0 = sigm(acc[mt][0][s2][q]     + bb[0][s2].x);
                    const float i1 = sigm(acc[mt][0][s2][q + 1] + bb[0][s2].y);
                    const float f0 = sigm(acc[mt][1][s2][q]     + bb[1][s2].x);
                    const float f1 = sigm(acc[mt][1][s2][q + 1] + bb[1][s2].y);
                    const float o0 = sigm(acc[mt][2][s2][q]     + bb[2][s2].x);
                    const float o1 = sigm(acc[mt][2][s2][q + 1] + bb[2][s2].y);
                    const float c0 = tanhf(acc[mt][3][s2][q]     + bb[3][s2].x);
                    const float c1 = tanhf(acc[mt][3][s2][q + 1] + bb[3][s2].y);

                    const float nc0 = f0 * cv.x + i0 * c0;
                    const float nc1 = f1 * cv.y + i1 * c1;
                    float2 oh, oc;
                    oc.x = nc0; oc.y = nc1;
                    oh.x = o0 * tanhf(nc0);
                    oh.y = o1 * tanhf(nc1);
                    *(float2*)(p.outh + ro + co) = oh;
                    *(float2*)(p.outc + ro + co) = oc;
                }
            }
        }
    }
}

// ---------------- launch ----------------
extern "C" void kernel_launch(void* const* d_in, const int* in_sizes, int n_in,
                              void* d_out, int out_size)
{
    (void)in_sizes; (void)n_in; (void)out_size;

    Params p;
    p.x = (const float*)d_in[0];
    p.h = (const float*)d_in[1];
    p.c = (const float*)d_in[2];
    for (int g = 0; g < 4; g++) {   // (Wi,bi,Ui),(Wf,bf,Uf),(Wo,bo,Uo),(Wc,bc,Uc)
        p.W[g]    = (const float*)d_in[3 + 3 * g];
        p.bias[g] = (const float*)d_in[4 + 3 * g];
        p.U[g]    = (const float*)d_in[5 + 3 * g];
    }
    float* out = (float*)d_out;
    p.outh = out;
    p.outc = out + (size_t)BATCH * DH;

    static bool configured = false;
    if (!configured) {
        cudaFuncSetAttribute(lstm_mma_tf32_kernel,
                             cudaFuncAttributeMaxDynamicSharedMemorySize, SMEM_BYTES);
        configured = true;
    }

    dim3 grid(DH / BNG, BATCH / BM);   // (16, 64)
    lstm_mma_tf32_kernel<<<grid, THREADS, SMEM_BYTES>>>(p);
}

// round 5
// speedup vs baseline: 6.1041x; 2.1111x over previous
#include <cuda_runtime.h>
#include <cuda_fp16.h>
#include <cstdint>

// ---------------- problem constants ----------------
constexpr int BATCH = 8192;
constexpr int DH    = 1024;

// ---------------- scratch (fp16 images of inputs) ----------------
// sA: [part(x=0,h=1)][8192][1024], sB: [part(W=0,U=1)][gate][1024][1024]
__device__ __align__(16) __half g_sA[2u * 8192u * 1024u];        // 32 MB
__device__ __align__(16) __half g_sB[2u * 4u * 1024u * 1024u];   // 16 MB

// ---------------- tiling ----------------
constexpr int BM      = 128;   // batch rows per CTA
constexpr int BNG     = 64;    // cols per gate per CTA
constexpr int NTOT    = 256;   // 4 gates x 64
constexpr int BK      = 64;    // K halfs per chunk (128B rows)
constexpr int KITERS  = 32;    // 2048 / 64
constexpr int NSTAGES = 4;
constexpr int THREADS = 512;   // 16 warps: 4(M) x 4(N)

constexpr int A_STAGE_BYTES = BM   * 128;                 // 16384
constexpr int B_STAGE_BYTES = NTOT * 128;                 // 32768
constexpr int STAGE_BYTES   = A_STAGE_BYTES + B_STAGE_BYTES;   // 49152
constexpr int SMEM_BYTES    = NSTAGES * STAGE_BYTES;           // 196608

struct Params {
    const float* x;
    const float* h;
    const float* c;
    const float* W[4];
    const float* U[4];
    const float* bias[4];
    float* outh;
    float* outc;
};

// ---------------- helpers ----------------
__device__ __forceinline__ uint32_t smem_u32(const void* p) {
    uint32_t a;
    asm("{ .reg .u64 t; cvta.to.shared.u64 t, %1; cvt.u32.u64 %0, t; }" : "=r"(a) : "l"(p));
    return a;
}
__device__ __forceinline__ void cp_async16(uint32_t dst, const void* src) {
    asm volatile("cp.async.cg.shared.global [%0], [%1], 16;" :: "r"(dst), "l"(src));
}
__device__ __forceinline__ void cp_commit() { asm volatile("cp.async.commit_group;"); }
template <int N> __device__ __forceinline__ void cp_wait() {
    asm volatile("cp.async.wait_group %0;" :: "n"(N));
}
__device__ __forceinline__ void ldsm_x4(uint32_t* r, uint32_t addr) {
    asm volatile("ldmatrix.sync.aligned.m8n8.x4.shared.b16 {%0,%1,%2,%3}, [%4];"
        : "=r"(r[0]), "=r"(r[1]), "=r"(r[2]), "=r"(r[3]) : "r"(addr));
}
__device__ __forceinline__ void mma_f16(float* d, const uint32_t* a, const uint32_t* b) {
    asm volatile(
        "mma.sync.aligned.m16n8k16.row.col.f32.f16.f16.f32 "
        "{%0,%1,%2,%3}, {%4,%5,%6,%7}, {%8,%9}, {%0,%1,%2,%3};"
        : "+f"(d[0]), "+f"(d[1]), "+f"(d[2]), "+f"(d[3])
        : "r"(a[0]), "r"(a[1]), "r"(a[2]), "r"(a[3]), "r"(b[0]), "r"(b[1]));
}
__device__ __forceinline__ float sigm(float v) { return 1.0f / (1.0f + __expf(-v)); }

// ---------------- pass 1: fp32 -> fp16 conversion ----------------
constexpr int XF4 = 8192 * 1024 / 4;   // float4 count for x (and h)
constexpr int GF4 = 1024 * 1024 / 4;   // float4 count per weight matrix
constexpr int TOTAL_F4 = 2 * XF4 + 8 * GF4;   // 6291456

__global__ void __launch_bounds__(256) convert_kernel(Params p)
{
    const int idx = blockIdx.x * 256 + threadIdx.x;
    if (idx >= TOTAL_F4) return;

    const float* src;
    __half* dst;
    if (idx < XF4) {
        src = p.x + (size_t)idx * 4;
        dst = g_sA + (size_t)idx * 4;
    } else if (idx < 2 * XF4) {
        const int t = idx - XF4;
        src = p.h + (size_t)t * 4;
        dst = g_sA + (size_t)(XF4 + t) * 4;
    } else {
        const int t = idx - 2 * XF4;
        const int r = t / GF4;          // 0..7 : W0..W3, U0..U3
        const int o = t - r * GF4;
        src = (r < 4 ? p.W[r] : p.U[r - 4]) + (size_t)o * 4;
        dst = g_sB + (size_t)r * (GF4 * 4) + (size_t)o * 4;
    }
    const float4 v = *(const float4*)src;
    __half2 h0 = __floats2half2_rn(v.x, v.y);
    __half2 h1 = __floats2half2_rn(v.z, v.w);
    uint2 pk;
    pk.x = *(const uint32_t*)&h0;
    pk.y = *(const uint32_t*)&h1;
    *(uint2*)dst = pk;
}

// ---------------- pass 2: fp16 GEMM + fused LSTM epilogue ----------------
__global__ void __launch_bounds__(THREADS, 1)
lstm_mma_f16_kernel(Params p)
{
    extern __shared__ __align__(128) char smem[];
    const uint32_t sbase = smem_u32(smem);

    const int tid  = threadIdx.x;
    const int wid  = tid >> 5;
    const int lane = tid & 31;
    const int wm   = wid >> 2;        // 0..3 : rows wm*32
    const int wn   = wid & 3;         // 0..3 : j cols wn*16 per gate
    const int g4   = lane >> 2;
    const int t4   = lane & 3;

    const int bm = blockIdx.y * BM;
    const int j0 = blockIdx.x * BNG;

    // ---- staging assignments: A 1024 chunks (2/thr), B 2048 chunks (4/thr) ----
    uint32_t a_dst[2]; uint32_t a_off[2];      // half offsets within part
    #pragma unroll
    for (int i = 0; i < 2; i++) {
        const int idx = tid + i * THREADS;
        const int r = idx >> 3, c = idx & 7;
        a_dst[i] = sbase + (uint32_t)(r * 128 + ((c ^ (r & 7)) << 4));
        a_off[i] = (uint32_t)(bm + r) * 1024u + (uint32_t)c * 8u;
    }
    uint32_t b_dst[4]; uint32_t b_off[4];
    #pragma unroll
    for (int i = 0; i < 4; i++) {
        const int idx = tid + i * THREADS;
        const int r = idx >> 3, c = idx & 7;        // r in [0,256)
        const int g = r >> 6, jl = r & 63;
        b_dst[i] = sbase + (uint32_t)(A_STAGE_BYTES + r * 128 + ((c ^ (r & 7)) << 4));
        b_off[i] = (uint32_t)g * (1024u * 1024u) + (uint32_t)(j0 + jl) * 1024u + (uint32_t)c * 8u;
    }

    auto stage = [&](int kn) {
        const uint32_t part = (uint32_t)(kn >> 4);               // 0: x/W, 1: h/U
        const uint32_t koff = (uint32_t)(kn & 15) * BK;          // half offset
        const uint32_t soff = (uint32_t)(kn & 3) * STAGE_BYTES;
        const __half* aP = g_sA + (size_t)part * (8192u * 1024u) + koff;
        const __half* bP = g_sB + (size_t)part * (4u * 1024u * 1024u) + koff;
        #pragma unroll
        for (int i = 0; i < 2; i++) cp_async16(a_dst[i] + soff, aP + a_off[i]);
        #pragma unroll
        for (int i = 0; i < 4; i++) cp_async16(b_dst[i] + soff, bP + b_off[i]);
    };

    // ---- accumulators ----
    float acc[2][4][2][4];
    #pragma unroll
    for (int a = 0; a < 2; a++)
        #pragma unroll
        for (int b = 0; b < 4; b++)
            #pragma unroll
            for (int s = 0; s < 2; s++)
                #pragma unroll
                for (int q = 0; q < 4; q++) acc[a][b][s][q] = 0.0f;

    // ---- per-lane ldmatrix row/col selection ----
    // A x4 quadrants -> a0(m0,k0) a1(m8,k0) a2(m0,k8) a3(m8,k8):
    //   lanes 0-7: m0-7 k0 | 8-15: m8-15 k0 | 16-23: m0-7 k8 | 24-31: m8-15 k8
    const int a_rsel = (lane & 7) + (((lane >> 3) & 1) << 3);
    const int a_ckad = (lane >> 4);
    // B smem is [n][k] (k contiguous) == exactly the mma B-fragment structure
    // (group = n, contiguous pair = k), so NON-trans ldmatrix, quadrants:
    //   r0(n0,k0)=b0s0  r1(n0,k8)=b1s0  r2(n8,k0)=b0s1  r3(n8,k8)=b1s1
    //   lanes 0-7: n0-7 k0 | 8-15: n0-7 k8 | 16-23: n8-15 k0 | 24-31: n8-15 k8
    const int b_rsel = (lane & 7) + ((lane >> 4) << 3);
    const int b_ckad = ((lane >> 3) & 1);

    int a_row[2], a_rx[2];
    #pragma unroll
    for (int mt = 0; mt < 2; mt++) {
        a_row[mt] = wm * 32 + mt * 16 + a_rsel;
        a_rx[mt]  = a_row[mt] & 7;
    }
    int b_row[4], b_rx[4];
    #pragma unroll
    for (int g = 0; g < 4; g++) {
        b_row[g] = g * 64 + wn * 16 + b_rsel;
        b_rx[g]  = b_row[g] & 7;
    }

    // ---- prologue ----
    #pragma unroll
    for (int kn = 0; kn < NSTAGES - 1; kn++) { stage(kn); cp_commit(); }

    // ---- main loop ----
    for (int kt = 0; kt < KITERS; kt++) {
        cp_wait<2>();
        __syncthreads();

        if (kt + NSTAGES - 1 < KITERS) stage(kt + NSTAGES - 1);
        cp_commit();

        const uint32_t As = sbase + (uint32_t)(kt & 3) * STAGE_BYTES;
        const uint32_t Bs = As + A_STAGE_BYTES;

        #pragma unroll
        for (int kk = 0; kk < 4; kk++) {
            uint32_t afr[2][4];
            #pragma unroll
            for (int mt = 0; mt < 2; mt++) {
                const int ck = kk * 2 + a_ckad;
                ldsm_x4(afr[mt], As + a_row[mt] * 128 + ((ck ^ a_rx[mt]) << 4));
            }
            uint32_t bfr[4][4];
            #pragma unroll
            for (int g = 0; g < 4; g++) {
                const int ck = kk * 2 + b_ckad;
                ldsm_x4(bfr[g], Bs + b_row[g] * 128 + ((ck ^ b_rx[g]) << 4));
            }
            #pragma unroll
            for (int mt = 0; mt < 2; mt++)
                #pragma unroll
                for (int g = 0; g < 4; g++) {
                    mma_f16(acc[mt][g][0], afr[mt], &bfr[g][0]);
                    mma_f16(acc[mt][g][1], afr[mt], &bfr[g][2]);
                }
        }
    }

    // ---- fused epilogue (register-resident) ----
    {
        float2 bb[4][2];
        #pragma unroll
        for (int g = 0; g < 4; g++)
            #pragma unroll
            for (int s2 = 0; s2 < 2; s2++)
                bb[g][s2] = *(const float2*)(p.bias[g] + j0 + wn * 16 + s2 * 8 + 2 * t4);

        #pragma unroll
        for (int mt = 0; mt < 2; mt++) {
            #pragma unroll
            for (int hh = 0; hh < 2; hh++) {
                const int row = bm + wm * 32 + mt * 16 + g4 + hh * 8;
                const size_t ro = (size_t)row * 1024 + j0 + wn * 16;
                #pragma unroll
                for (int s2 = 0; s2 < 2; s2++) {
                    const int co = s2 * 8 + 2 * t4;
                    const float2 cv = *(const float2*)(p.c + ro + co);
                    const int q = hh * 2;

                    const float i0 = sigm(acc[mt][0][s2][q]     + bb[0][s2].x);
                    const float i1 = sigm(acc[mt][0][s2][q + 1] + bb[0][s2].y);
                    const float f0 = sigm(acc[mt][1][s2][q]     + bb[1][s2].x);
                    const float f1 = sigm(acc[mt][1][s2][q + 1] + bb[1][s2].y);
                    const float o0 = sigm(acc[mt][2][s2][q]     + bb[2][s2].x);
                    const float o1 = sigm(acc[mt][2][s2][q + 1] + bb[2][s2].y);
                    const float c0 = tanhf(acc[mt][3][s2][q]     + bb[3][s2].x);
                    const float c1 = tanhf(acc[mt][3][s2][q + 1] + bb[3][s2].y);

                    const float nc0 = f0 * cv.x + i0 * c0;
                    const float nc1 = f1 * cv.y + i1 * c1;
                    float2 oh, oc;
                    oc.x = nc0; oc.y = nc1;
                    oh.x = o0 * tanhf(nc0);
                    oh.y = o1 * tanhf(nc1);
                    *(float2*)(p.outh + ro + co) = oh;
                    *(float2*)(p.outc + ro + co) = oc;
                }
            }
        }
    }
}

// ---------------- launch ----------------
extern "C" void kernel_launch(void* const* d_in, const int* in_sizes, int n_in,
                              void* d_out, int out_size)
{
    (void)in_sizes; (void)n_in; (void)out_size;

    Params p;
    p.x = (const float*)d_in[0];
    p.h = (const float*)d_in[1];
    p.c = (const float*)d_in[2];
    for (int g = 0; g < 4; g++) {   // (Wi,bi,Ui),(Wf,bf,Uf),(Wo,bo,Uo),(Wc,bc,Uc)
        p.W[g]    = (const float*)d_in[3 + 3 * g];
        p.bias[g] = (const float*)d_in[4 + 3 * g];
        p.U[g]    = (const float*)d_in[5 + 3 * g];
    }
    float* out = (float*)d_out;
    p.outh = out;
    p.outc = out + (size_t)BATCH * DH;

    static bool configured = false;
    if (!configured) {
        cudaFuncSetAttribute(lstm_mma_f16_kernel,
                             cudaFuncAttributeMaxDynamicSharedMemorySize, SMEM_BYTES);
        configured = true;
    }

    convert_kernel<<<(TOTAL_F4 + 255) / 256, 256>>>(p);

    dim3 grid(DH / BNG, BATCH / BM);   // (16, 64)
    lstm_mma_f16_kernel<<<grid, THREADS, SMEM_BYTES>>>(p);
}

// round 6
// speedup vs baseline: 6.6157x; 1.0838x over previous
#include <cuda_runtime.h>
#include <cuda_fp16.h>
#include <cstdint>

// ---------------- problem constants ----------------
constexpr int BATCH = 8192;
constexpr int DH    = 1024;

// ---------------- scratch (fp16 images of inputs) ----------------
// sA: [part(x=0,h=1)][8192][1024], sB: [part(W=0,U=1)][gate][1024][1024]
__device__ __align__(16) __half g_sA[2u * 8192u * 1024u];        // 32 MB
__device__ __align__(16) __half g_sB[2u * 4u * 1024u * 1024u];   // 16 MB

// ---------------- tiling ----------------
constexpr int BM      = 128;   // batch rows per CTA
constexpr int BNG     = 32;    // cols per gate per CTA
constexpr int NTOT    = 128;   // 4 gates x 32
constexpr int BK      = 64;    // K halfs per chunk (128B rows)
constexpr int KITERS  = 32;    // 2048 / 64
constexpr int NSTAGES = 3;
constexpr int THREADS = 256;   // 8 warps: 4(M) x 2(N)

constexpr int A_STAGE_BYTES = BM   * 128;                 // 16384
constexpr int B_STAGE_BYTES = NTOT * 128;                 // 16384
constexpr int STAGE_BYTES   = A_STAGE_BYTES + B_STAGE_BYTES;   // 32768
constexpr int SMEM_BYTES    = NSTAGES * STAGE_BYTES;           // 98304 -> 2 CTAs/SM

struct Params {
    const float* x;
    const float* h;
    const float* c;
    const float* W[4];
    const float* U[4];
    const float* bias[4];
    float* outh;
    float* outc;
};

// ---------------- helpers ----------------
__device__ __forceinline__ uint32_t smem_u32(const void* p) {
    uint32_t a;
    asm("{ .reg .u64 t; cvta.to.shared.u64 t, %1; cvt.u32.u64 %0, t; }" : "=r"(a) : "l"(p));
    return a;
}
__device__ __forceinline__ void cp_async16(uint32_t dst, const void* src) {
    asm volatile("cp.async.cg.shared.global [%0], [%1], 16;" :: "r"(dst), "l"(src));
}
__device__ __forceinline__ void cp_commit() { asm volatile("cp.async.commit_group;"); }
template <int N> __device__ __forceinline__ void cp_wait() {
    asm volatile("cp.async.wait_group %0;" :: "n"(N));
}
__device__ __forceinline__ void ldsm_x4(uint32_t* r, uint32_t addr) {
    asm volatile("ldmatrix.sync.aligned.m8n8.x4.shared.b16 {%0,%1,%2,%3}, [%4];"
        : "=r"(r[0]), "=r"(r[1]), "=r"(r[2]), "=r"(r[3]) : "r"(addr));
}
__device__ __forceinline__ void mma_f16(float* d, const uint32_t* a, const uint32_t* b) {
    asm volatile(
        "mma.sync.aligned.m16n8k16.row.col.f32.f16.f16.f32 "
        "{%0,%1,%2,%3}, {%4,%5,%6,%7}, {%8,%9}, {%0,%1,%2,%3};"
        : "+f"(d[0]), "+f"(d[1]), "+f"(d[2]), "+f"(d[3])
        : "r"(a[0]), "r"(a[1]), "r"(a[2]), "r"(a[3]), "r"(b[0]), "r"(b[1]));
}
__device__ __forceinline__ float sigm(float v) { return 1.0f / (1.0f + __expf(-v)); }

// ---------------- pass 1: fp32 -> fp16 conversion ----------------
constexpr int XF4 = 8192 * 1024 / 4;   // float4 count for x (and h)
constexpr int GF4 = 1024 * 1024 / 4;   // float4 count per weight matrix
constexpr int TOTAL_F4 = 2 * XF4 + 8 * GF4;   // 6291456

__global__ void __launch_bounds__(256) convert_kernel(Params p)
{
    const int idx = blockIdx.x * 256 + threadIdx.x;
    if (idx >= TOTAL_F4) return;

    const float* src;
    __half* dst;
    if (idx < XF4) {
        src = p.x + (size_t)idx * 4;
        dst = g_sA + (size_t)idx * 4;
    } else if (idx < 2 * XF4) {
        const int t = idx - XF4;
        src = p.h + (size_t)t * 4;
        dst = g_sA + (size_t)(XF4 + t) * 4;
    } else {
        const int t = idx - 2 * XF4;
        const int r = t / GF4;          // 0..7 : W0..W3, U0..U3
        const int o = t - r * GF4;
        src = (r < 4 ? p.W[r] : p.U[r - 4]) + (size_t)o * 4;
        dst = g_sB + (size_t)r * (GF4 * 4) + (size_t)o * 4;
    }
    const float4 v = *(const float4*)src;
    __half2 h0 = __floats2half2_rn(v.x, v.y);
    __half2 h1 = __floats2half2_rn(v.z, v.w);
    uint2 pk;
    pk.x = *(const uint32_t*)&h0;
    pk.y = *(const uint32_t*)&h1;
    *(uint2*)dst = pk;
}

// ---------------- pass 2: fp16 GEMM + fused LSTM epilogue ----------------
__global__ void __launch_bounds__(THREADS, 2)
lstm_mma_f16_kernel(Params p)
{
    extern __shared__ __align__(128) char smem[];
    const uint32_t sbase = smem_u32(smem);

    const int tid  = threadIdx.x;
    const int wid  = tid >> 5;
    const int lane = tid & 31;
    const int wm   = wid >> 1;        // 0..3 : rows wm*32
    const int wn   = wid & 1;         // 0..1 : j cols wn*16 per gate
    const int g4   = lane >> 2;
    const int t4   = lane & 3;

    const int bm = blockIdx.y * BM;
    const int j0 = blockIdx.x * BNG;

    // ---- staging assignments: A 1024 16B-chunks (4/thr), B 1024 (4/thr) ----
    uint32_t a_dst[4]; uint32_t a_off[4];      // half offsets within part
    #pragma unroll
    for (int i = 0; i < 4; i++) {
        const int idx = tid + i * THREADS;     // 0..1023
        const int r = idx >> 3, c = idx & 7;
        a_dst[i] = sbase + (uint32_t)(r * 128 + ((c ^ (r & 7)) << 4));
        a_off[i] = (uint32_t)(bm + r) * 1024u + (uint32_t)c * 8u;
    }
    uint32_t b_dst[4]; uint32_t b_off[4];
    #pragma unroll
    for (int i = 0; i < 4; i++) {
        const int idx = tid + i * THREADS;     // 0..1023
        const int r = idx >> 3, c = idx & 7;   // r in [0,128)
        const int g = r >> 5, jl = r & 31;
        b_dst[i] = sbase + (uint32_t)(A_STAGE_BYTES + r * 128 + ((c ^ (r & 7)) << 4));
        b_off[i] = (uint32_t)g * (1024u * 1024u) + (uint32_t)(j0 + jl) * 1024u + (uint32_t)c * 8u;
    }

    auto stage = [&](int kn) {
        const uint32_t part = (uint32_t)(kn >> 4);               // 0: x/W, 1: h/U
        const uint32_t koff = (uint32_t)(kn & 15) * BK;          // half offset
        const uint32_t soff = (uint32_t)(kn % NSTAGES) * STAGE_BYTES;
        const __half* aP = g_sA + (size_t)part * (8192u * 1024u) + koff;
        const __half* bP = g_sB + (size_t)part * (4u * 1024u * 1024u) + koff;
        #pragma unroll
        for (int i = 0; i < 4; i++) cp_async16(a_dst[i] + soff, aP + a_off[i]);
        #pragma unroll
        for (int i = 0; i < 4; i++) cp_async16(b_dst[i] + soff, bP + b_off[i]);
    };

    // ---- accumulators ----
    float acc[2][4][2][4];
    #pragma unroll
    for (int a = 0; a < 2; a++)
        #pragma unroll
        for (int b = 0; b < 4; b++)
            #pragma unroll
            for (int s = 0; s < 2; s++)
                #pragma unroll
                for (int q = 0; q < 4; q++) acc[a][b][s][q] = 0.0f;

    // ---- per-lane ldmatrix row/col selection ----
    const int a_rsel = (lane & 7) + (((lane >> 3) & 1) << 3);
    const int a_ckad = (lane >> 4);
    const int b_rsel = (lane & 7) + ((lane >> 4) << 3);
    const int b_ckad = ((lane >> 3) & 1);

    int a_row[2], a_rx[2];
    #pragma unroll
    for (int mt = 0; mt < 2; mt++) {
        a_row[mt] = wm * 32 + mt * 16 + a_rsel;
        a_rx[mt]  = a_row[mt] & 7;
    }
    int b_row[4], b_rx[4];
    #pragma unroll
    for (int g = 0; g < 4; g++) {
        b_row[g] = g * 32 + wn * 16 + b_rsel;
        b_rx[g]  = b_row[g] & 7;
    }

    // ---- prologue: stage chunks 0,1 ----
    #pragma unroll
    for (int kn = 0; kn < NSTAGES - 1; kn++) { stage(kn); cp_commit(); }

    // ---- main loop ----
    for (int kt = 0; kt < KITERS; kt++) {
        cp_wait<1>();
        __syncthreads();

        if (kt + NSTAGES - 1 < KITERS) stage(kt + NSTAGES - 1);
        cp_commit();

        const uint32_t As = sbase + (uint32_t)(kt % NSTAGES) * STAGE_BYTES;
        const uint32_t Bs = As + A_STAGE_BYTES;

        #pragma unroll
        for (int kk = 0; kk < 4; kk++) {
            uint32_t afr[2][4];
            #pragma unroll
            for (int mt = 0; mt < 2; mt++) {
                const int ck = kk * 2 + a_ckad;
                ldsm_x4(afr[mt], As + a_row[mt] * 128 + ((ck ^ a_rx[mt]) << 4));
            }
            uint32_t bfr[4][4];
            #pragma unroll
            for (int g = 0; g < 4; g++) {
                const int ck = kk * 2 + b_ckad;
                ldsm_x4(bfr[g], Bs + b_row[g] * 128 + ((ck ^ b_rx[g]) << 4));
            }
            #pragma unroll
            for (int mt = 0; mt < 2; mt++)
                #pragma unroll
                for (int g = 0; g < 4; g++) {
                    mma_f16(acc[mt][g][0], afr[mt], &bfr[g][0]);
                    mma_f16(acc[mt][g][1], afr[mt], &bfr[g][2]);
                }
        }
    }

    // ---- fused epilogue (register-resident) ----
    {
        float2 bb[4][2];
        #pragma unroll
        for (int g = 0; g < 4; g++)
            #pragma unroll
            for (int s2 = 0; s2 < 2; s2++)
                bb[g][s2] = *(const float2*)(p.bias[g] + j0 + wn * 16 + s2 * 8 + 2 * t4);

        #pragma unroll
        for (int mt = 0; mt < 2; mt++) {
            #pragma unroll
            for (int hh = 0; hh < 2; hh++) {
                const int row = bm + wm * 32 + mt * 16 + g4 + hh * 8;
                const size_t ro = (size_t)row * 1024 + j0 + wn * 16;
                #pragma unroll
                for (int s2 = 0; s2 < 2; s2++) {
                    const int co = s2 * 8 + 2 * t4;
                    const float2 cv = *(const float2*)(p.c + ro + co);
                    const int q = hh * 2;

                    const float i0 = sigm(acc[mt][0][s2][q]     + bb[0][s2].x);
                    const float i1 = sigm(acc[mt][0][s2][q + 1] + bb[0][s2].y);
                    const float f0 = sigm(acc[mt][1][s2][q]     + bb[1][s2].x);
                    const float f1 = sigm(acc[mt][1][s2][q + 1] + bb[1][s2].y);
                    const float o0 = sigm(acc[mt][2][s2][q]     + bb[2][s2].x);
                    const float o1 = sigm(acc[mt][2][s2][q + 1] + bb[2][s2].y);
                    const float c0 = tanhf(acc[mt][3][s2][q]     + bb[3][s2].x);
                    const float c1 = tanhf(acc[mt][3][s2][q + 1] + bb[3][s2].y);

                    const float nc0 = f0 * cv.x + i0 * c0;
                    const float nc1 = f1 * cv.y + i1 * c1;
                    float2 oh, oc;
                    oc.x = nc0; oc.y = nc1;
                    oh.x = o0 * tanhf(nc0);
                    oh.y = o1 * tanhf(nc1);
                    *(float2*)(p.outh + ro + co) = oh;
                    *(float2*)(p.outc + ro + co) = oc;
                }
            }
        }
    }
}

// ---------------- launch ----------------
extern "C" void kernel_launch(void* const* d_in, const int* in_sizes, int n_in,
                              void* d_out, int out_size)
{
    (void)in_sizes; (void)n_in; (void)out_size;

    Params p;
    p.x = (const float*)d_in[0];
    p.h = (const float*)d_in[1];
    p.c = (const float*)d_in[2];
    for (int g = 0; g < 4; g++) {   // (Wi,bi,Ui),(Wf,bf,Uf),(Wo,bo,Uo),(Wc,bc,Uc)
        p.W[g]    = (const float*)d_in[3 + 3 * g];
        p.bias[g] = (const float*)d_in[4 + 3 * g];
        p.U[g]    = (const float*)d_in[5 + 3 * g];
    }
    float* out = (float*)d_out;
    p.outh = out;
    p.outc = out + (size_t)BATCH * DH;

    static bool configured = false;
    if (!configured) {
        cudaFuncSetAttribute(lstm_mma_f16_kernel,
                             cudaFuncAttributeMaxDynamicSharedMemorySize, SMEM_BYTES);
        configured = true;
    }

    convert_kernel<<<(TOTAL_F4 + 255) / 256, 256>>>(p);

    dim3 grid(DH / BNG, BATCH / BM);   // (32, 64)
    lstm_mma_f16_kernel<<<grid, THREADS, SMEM_BYTES>>>(p);
}

// round 7
// speedup vs baseline: 7.3873x; 1.1166x over previous
#include <cuda_runtime.h>
#include <cuda_fp16.h>
#include <cstdint>

// ---------------- problem constants ----------------
constexpr int BATCH = 8192;
constexpr int DH    = 1024;

// ---------------- scratch (fp16 images of inputs) ----------------
// sA: [part(x=0,h=1)][8192][1024], sB: [part(W=0,U=1)][gate][1024][1024]
__device__ __align__(16) __half g_sA[2u * 8192u * 1024u];        // 32 MB
__device__ __align__(16) __half g_sB[2u * 4u * 1024u * 1024u];   // 16 MB

// ---------------- tiling ----------------
constexpr int BM      = 128;   // batch rows per CTA
constexpr int BNG     = 32;    // cols per gate per CTA
constexpr int NTOT    = 128;   // 4 gates x 32
constexpr int BK      = 64;    // K halfs per chunk (128B rows)
constexpr int KITERS  = 32;    // 2048 / 64
constexpr int NSTAGES = 3;
constexpr int THREADS = 256;   // 8 warps: 4(M) x 2(N)

constexpr int A_STAGE_BYTES = BM   * 128;                 // 16384
constexpr int B_STAGE_BYTES = NTOT * 128;                 // 16384
constexpr int STAGE_BYTES   = A_STAGE_BYTES + B_STAGE_BYTES;   // 32768
constexpr int SMEM_BYTES    = NSTAGES * STAGE_BYTES;           // 98304 -> 2 CTAs/SM

template <int N> struct IC { static constexpr int value = N; };

struct Params {
    const float* x;
    const float* h;
    const float* c;
    const float* W[4];
    const float* U[4];
    const float* bias[4];
    float* outh;
    float* outc;
};

// ---------------- helpers ----------------
__device__ __forceinline__ uint32_t smem_u32(const void* p) {
    uint32_t a;
    asm("{ .reg .u64 t; cvta.to.shared.u64 t, %1; cvt.u32.u64 %0, t; }" : "=r"(a) : "l"(p));
    return a;
}
__device__ __forceinline__ void cp_async16(uint32_t dst, const void* src) {
    asm volatile("cp.async.cg.shared.global [%0], [%1], 16;" :: "r"(dst), "l"(src));
}
__device__ __forceinline__ void cp_commit() { asm volatile("cp.async.commit_group;"); }
template <int N> __device__ __forceinline__ void cp_wait() {
    asm volatile("cp.async.wait_group %0;" :: "n"(N));
}
__device__ __forceinline__ void ldsm_x4(uint32_t* r, uint32_t addr) {
    asm volatile("ldmatrix.sync.aligned.m8n8.x4.shared.b16 {%0,%1,%2,%3}, [%4];"
        : "=r"(r[0]), "=r"(r[1]), "=r"(r[2]), "=r"(r[3]) : "r"(addr));
}
__device__ __forceinline__ void mma_f16(float* d, const uint32_t* a, const uint32_t* b) {
    asm volatile(
        "mma.sync.aligned.m16n8k16.row.col.f32.f16.f16.f32 "
        "{%0,%1,%2,%3}, {%4,%5,%6,%7}, {%8,%9}, {%0,%1,%2,%3};"
        : "+f"(d[0]), "+f"(d[1]), "+f"(d[2]), "+f"(d[3])
        : "r"(a[0]), "r"(a[1]), "r"(a[2]), "r"(a[3]), "r"(b[0]), "r"(b[1]));
}
__device__ __forceinline__ float sigm(float v) {
    return __fdividef(1.0f, 1.0f + __expf(-v));
}
__device__ __forceinline__ float ftanh(float v) {
    return __fmaf_rn(2.0f, sigm(2.0f * v), -1.0f);
}

// ---------------- pass 1: fp32 -> fp16 conversion ----------------
constexpr int XF4 = 8192 * 1024 / 4;   // float4 count for x (and h)
constexpr int GF4 = 1024 * 1024 / 4;   // float4 count per weight matrix
constexpr int TOTAL_F4 = 2 * XF4 + 8 * GF4;   // 6291456

__global__ void __launch_bounds__(256) convert_kernel(Params p)
{
    const int idx = blockIdx.x * 256 + threadIdx.x;
    if (idx >= TOTAL_F4) return;

    const float* src;
    __half* dst;
    if (idx < XF4) {
        src = p.x + (size_t)idx * 4;
        dst = g_sA + (size_t)idx * 4;
    } else if (idx < 2 * XF4) {
        const int t = idx - XF4;
        src = p.h + (size_t)t * 4;
        dst = g_sA + (size_t)(XF4 + t) * 4;
    } else {
        const int t = idx - 2 * XF4;
        const int r = t / GF4;          // 0..7 : W0..W3, U0..U3
        const int o = t - r * GF4;
        src = (r < 4 ? p.W[r] : p.U[r - 4]) + (size_t)o * 4;
        dst = g_sB + (size_t)r * (GF4 * 4) + (size_t)o * 4;
    }
    const float4 v = *(const float4*)src;
    __half2 h0 = __floats2half2_rn(v.x, v.y);
    __half2 h1 = __floats2half2_rn(v.z, v.w);
    uint2 pk;
    pk.x = *(const uint32_t*)&h0;
    pk.y = *(const uint32_t*)&h1;
    *(uint2*)dst = pk;
}

// ---------------- pass 2: fp16 GEMM + fused LSTM epilogue ----------------
__global__ void __launch_bounds__(THREADS, 2)
lstm_mma_f16_kernel(Params p)
{
    extern __shared__ __align__(128) char smem[];
    const uint32_t sbase = smem_u32(smem);

    const int tid  = threadIdx.x;
    const int wid  = tid >> 5;
    const int lane = tid & 31;
    const int wm   = wid >> 1;        // 0..3 : rows wm*32
    const int wn   = wid & 1;         // 0..1 : j cols wn*16 per gate
    const int g4   = lane >> 2;
    const int t4   = lane & 3;

    const int bm = blockIdx.y * BM;
    const int j0 = blockIdx.x * BNG;

    // ---- staging assignments: A 1024 16B-chunks (4/thr), B 1024 (4/thr) ----
    uint32_t a_dst[4]; uint32_t a_off[4];      // half offsets within part
    #pragma unroll
    for (int i = 0; i < 4; i++) {
        const int idx = tid + i * THREADS;     // 0..1023
        const int r = idx >> 3, c = idx & 7;
        a_dst[i] = sbase + (uint32_t)(r * 128 + ((c ^ (r & 7)) << 4));
        a_off[i] = (uint32_t)(bm + r) * 1024u + (uint32_t)c * 8u;
    }
    uint32_t b_dst[4]; uint32_t b_off[4];
    #pragma unroll
    for (int i = 0; i < 4; i++) {
        const int idx = tid + i * THREADS;     // 0..1023
        const int r = idx >> 3, c = idx & 7;   // r in [0,128)
        const int g = r >> 5, jl = r & 31;
        b_dst[i] = sbase + (uint32_t)(A_STAGE_BYTES + r * 128 + ((c ^ (r & 7)) << 4));
        b_off[i] = (uint32_t)g * (1024u * 1024u) + (uint32_t)(j0 + jl) * 1024u + (uint32_t)c * 8u;
    }

    // stage chunk kn into buffer SS (compile-time)
    auto stage_s = [&](auto Sc, int kn) {
        constexpr uint32_t soff = (uint32_t)decltype(Sc)::value * STAGE_BYTES;
        const uint32_t part = (uint32_t)(kn >> 4);               // 0: x/W, 1: h/U
        const uint32_t koff = (uint32_t)(kn & 15) * BK;          // half offset
        const __half* aP = g_sA + (size_t)part * (8192u * 1024u) + koff;
        const __half* bP = g_sB + (size_t)part * (4u * 1024u * 1024u) + koff;
        #pragma unroll
        for (int i = 0; i < 4; i++) cp_async16(a_dst[i] + soff, aP + a_off[i]);
        #pragma unroll
        for (int i = 0; i < 4; i++) cp_async16(b_dst[i] + soff, bP + b_off[i]);
    };

    // ---- accumulators ----
    float acc[2][4][2][4];
    #pragma unroll
    for (int a = 0; a < 2; a++)
        #pragma unroll
        for (int b = 0; b < 4; b++)
            #pragma unroll
            for (int s = 0; s < 2; s++)
                #pragma unroll
                for (int q = 0; q < 4; q++) acc[a][b][s][q] = 0.0f;

    // ---- per-lane ldmatrix row/col selection ----
    const int a_rsel = (lane & 7) + (((lane >> 3) & 1) << 3);
    const int a_ckad = (lane >> 4);
    const int b_rsel = (lane & 7) + ((lane >> 4) << 3);
    const int b_ckad = ((lane >> 3) & 1);

    uint32_t a_base[2]; int a_rx[2];
    #pragma unroll
    for (int mt = 0; mt < 2; mt++) {
        const int row = wm * 32 + mt * 16 + a_rsel;
        a_base[mt] = sbase + (uint32_t)(row * 128);
        a_rx[mt]   = row & 7;
    }
    uint32_t b_base[4]; int b_rx[4];
    #pragma unroll
    for (int g = 0; g < 4; g++) {
        const int row = g * 32 + wn * 16 + b_rsel;
        b_base[g] = sbase + (uint32_t)(A_STAGE_BYTES + row * 128);
        b_rx[g]   = row & 7;
    }

    // one pipeline step: compute chunk kt from buffer S, stage chunk kt+2 into (S+2)%3
    auto body = [&](auto Sc, int kt) {
        constexpr int S = decltype(Sc)::value;
        cp_wait<1>();
        __syncthreads();

        const int kn = kt + NSTAGES - 1;
        if (kn < KITERS) stage_s(IC<(S + 2) % 3>{}, kn);
        cp_commit();

        constexpr uint32_t soff = (uint32_t)S * STAGE_BYTES;

        #pragma unroll
        for (int kk = 0; kk < 4; kk++) {
            uint32_t afr[2][4];
            #pragma unroll
            for (int mt = 0; mt < 2; mt++) {
                const int ck = kk * 2 + a_ckad;
                ldsm_x4(afr[mt], a_base[mt] + soff + ((ck ^ a_rx[mt]) << 4));
            }
            uint32_t bfr[4][4];
            #pragma unroll
            for (int g = 0; g < 4; g++) {
                const int ck = kk * 2 + b_ckad;
                ldsm_x4(bfr[g], b_base[g] + soff + ((ck ^ b_rx[g]) << 4));
            }
            #pragma unroll
            for (int mt = 0; mt < 2; mt++)
                #pragma unroll
                for (int g = 0; g < 4; g++) {
                    mma_f16(acc[mt][g][0], afr[mt], &bfr[g][0]);
                    mma_f16(acc[mt][g][1], afr[mt], &bfr[g][2]);
                }
        }
    };

    // ---- prologue: stage chunks 0,1 ----
    stage_s(IC<0>{}, 0); cp_commit();
    stage_s(IC<1>{}, 1); cp_commit();

    // ---- main loop: 32 chunks = 10 x 3 + 2 ----
    for (int base = 0; base < 30; base += 3) {
        body(IC<0>{}, base);
        body(IC<1>{}, base + 1);
        body(IC<2>{}, base + 2);
    }
    body(IC<0>{}, 30);
    body(IC<1>{}, 31);

    // ---- fused epilogue (register-resident) ----
    {
        float2 bb[4][2];
        #pragma unroll
        for (int g = 0; g < 4; g++)
            #pragma unroll
            for (int s2 = 0; s2 < 2; s2++)
                bb[g][s2] = *(const float2*)(p.bias[g] + j0 + wn * 16 + s2 * 8 + 2 * t4);

        #pragma unroll
        for (int mt = 0; mt < 2; mt++) {
            #pragma unroll
            for (int hh = 0; hh < 2; hh++) {
                const int row = bm + wm * 32 + mt * 16 + g4 + hh * 8;
                const size_t ro = (size_t)row * 1024 + j0 + wn * 16;
                #pragma unroll
                for (int s2 = 0; s2 < 2; s2++) {
                    const int co = s2 * 8 + 2 * t4;
                    const float2 cv = *(const float2*)(p.c + ro + co);
                    const int q = hh * 2;

                    const float i0 = sigm(acc[mt][0][s2][q]     + bb[0][s2].x);
                    const float i1 = sigm(acc[mt][0][s2][q + 1] + bb[0][s2].y);
                    const float f0 = sigm(acc[mt][1][s2][q]     + bb[1][s2].x);
                    const float f1 = sigm(acc[mt][1][s2][q + 1] + bb[1][s2].y);
                    const float o0 = sigm(acc[mt][2][s2][q]     + bb[2][s2].x);
                    const float o1 = sigm(acc[mt][2][s2][q + 1] + bb[2][s2].y);
                    const float c0 = ftanh(acc[mt][3][s2][q]     + bb[3][s2].x);
                    const float c1 = ftanh(acc[mt][3][s2][q + 1] + bb[3][s2].y);

                    const float nc0 = f0 * cv.x + i0 * c0;
                    const float nc1 = f1 * cv.y + i1 * c1;
                    float2 oh, oc;
                    oc.x = nc0; oc.y = nc1;
                    oh.x = o0 * ftanh(nc0);
                    oh.y = o1 * ftanh(nc1);
                    *(float2*)(p.outh + ro + co) = oh;
                    *(float2*)(p.outc + ro + co) = oc;
                }
            }
        }
    }
}

// ---------------- launch ----------------
extern "C" void kernel_launch(void* const* d_in, const int* in_sizes, int n_in,
                              void* d_out, int out_size)
{
    (void)in_sizes; (void)n_in; (void)out_size;

    Params p;
    p.x = (const float*)d_in[0];
    p.h = (const float*)d_in[1];
    p.c = (const float*)d_in[2];
    for (int g = 0; g < 4; g++) {   // (Wi,bi,Ui),(Wf,bf,Uf),(Wo,bo,Uo),(Wc,bc,Uc)
        p.W[g]    = (const float*)d_in[3 + 3 * g];
        p.bias[g] = (const float*)d_in[4 + 3 * g];
        p.U[g]    = (const float*)d_in[5 + 3 * g];
    }
    float* out = (float*)d_out;
    p.outh = out;
    p.outc = out + (size_t)BATCH * DH;

    static bool configured = false;
    if (!configured) {
        cudaFuncSetAttribute(lstm_mma_f16_kernel,
                             cudaFuncAttributeMaxDynamicSharedMemorySize, SMEM_BYTES);
        configured = true;
    }

    convert_kernel<<<(TOTAL_F4 + 255) / 256, 256>>>(p);

    dim3 grid(DH / BNG, BATCH / BM);   // (32, 64)
    lstm_mma_f16_kernel<<<grid, THREADS, SMEM_BYTES>>>(p);
}

// round 8
// speedup vs baseline: 8.4395x; 1.1424x over previous
#include <cuda_runtime.h>
#include <cuda_fp16.h>
#include <cstdint>

// ---------------- problem constants ----------------
constexpr int BATCH = 8192;
constexpr int DH    = 1024;

// ---------------- tiling ----------------
constexpr int BM      = 128;   // batch rows per CTA
constexpr int BNG     = 32;    // cols per gate per CTA
constexpr int NTOT    = 128;   // 4 gates x 32
constexpr int BK      = 64;    // K halfs per chunk (128B rows)
constexpr int KITERS  = 32;    // 2048 / 64
constexpr int THREADS = 256;   // 8 warps: 4(M) x 2(N)

constexpr int A_STAGE_BYTES = BM   * 128;                 // 16384
constexpr int B_STAGE_BYTES = NTOT * 128;                 // 16384
constexpr int STAGE_BYTES   = A_STAGE_BYTES + B_STAGE_BYTES;   // 32768
constexpr int MBAR_OFF      = 3 * STAGE_BYTES;                 // 98304
constexpr int SMEM_BYTES    = MBAR_OFF + 64;                   // 98368 -> 2 CTAs/SM

// ---------------- scratch: pre-tiled + pre-swizzled fp16 ----------------
// A: [bt(64)][chunk(32)][128 rows x 128B, XOR-swizzled]  (chunks 0-15: x, 16-31: h)
// B: [jt(32)][chunk(32)][128 rows (g*32+jl) x 128B, XOR-swizzled]
__device__ __align__(128) __half g_sA[64u * 32u * 8192u];   // 32 MB
__device__ __align__(128) __half g_sB[32u * 32u * 8192u];   // 16 MB

template <int N> struct IC { static constexpr int value = N; };

struct Params {
    const float* x;
    const float* h;
    const float* c;
    const float* W[4];
    const float* U[4];
    const float* bias[4];
    float* outh;
    float* outc;
};

// ---------------- helpers ----------------
__device__ __forceinline__ uint32_t smem_u32(const void* p) {
    uint32_t a;
    asm("{ .reg .u64 t; cvta.to.shared.u64 t, %1; cvt.u32.u64 %0, t; }" : "=r"(a) : "l"(p));
    return a;
}
__device__ __forceinline__ void mbar_init(uint32_t a, uint32_t cnt) {
    asm volatile("mbarrier.init.shared.b64 [%0], %1;" :: "r"(a), "r"(cnt) : "memory");
}
__device__ __forceinline__ void mbar_arrive(uint32_t a) {
    asm volatile("mbarrier.arrive.shared.b64 _, [%0];" :: "r"(a) : "memory");
}
__device__ __forceinline__ void mbar_expect_tx(uint32_t a, uint32_t tx) {
    asm volatile("mbarrier.arrive.expect_tx.shared.b64 _, [%0], %1;" :: "r"(a), "r"(tx) : "memory");
}
__device__ __forceinline__ void mbar_wait(uint32_t a, uint32_t parity) {
    asm volatile(
        "{\n\t.reg .pred P;\n"
        "W%=:\n\t"
        "mbarrier.try_wait.parity.shared::cta.b64 P, [%0], %1, 0x989680;\n\t"
        "@!P bra W%=;\n\t}"
        :: "r"(a), "r"(parity) : "memory");
}
__device__ __forceinline__ void bulk_g2s(uint32_t dst, const void* src, uint32_t bytes, uint32_t mbar) {
    asm volatile(
        "cp.async.bulk.shared::cluster.global.mbarrier::complete_tx::bytes [%0], [%1], %2, [%3];"
        :: "r"(dst), "l"(src), "r"(bytes), "r"(mbar) : "memory");
}
__device__ __forceinline__ void ldsm_x4(uint32_t* r, uint32_t addr) {
    asm volatile("ldmatrix.sync.aligned.m8n8.x4.shared.b16 {%0,%1,%2,%3}, [%4];"
        : "=r"(r[0]), "=r"(r[1]), "=r"(r[2]), "=r"(r[3]) : "r"(addr));
}
__device__ __forceinline__ void mma_f16(float* d, const uint32_t* a, const uint32_t* b) {
    asm volatile(
        "mma.sync.aligned.m16n8k16.row.col.f32.f16.f16.f32 "
        "{%0,%1,%2,%3}, {%4,%5,%6,%7}, {%8,%9}, {%0,%1,%2,%3};"
        : "+f"(d[0]), "+f"(d[1]), "+f"(d[2]), "+f"(d[3])
        : "r"(a[0]), "r"(a[1]), "r"(a[2]), "r"(a[3]), "r"(b[0]), "r"(b[1]));
}
__device__ __forceinline__ float sigm(float v) {
    return __fdividef(1.0f, 1.0f + __expf(-v));
}
__device__ __forceinline__ float ftanh(float v) {
    return __fmaf_rn(2.0f, sigm(2.0f * v), -1.0f);
}

// ---------------- pass 1: fp32 -> tiled/swizzled fp16 ----------------
constexpr int ACH = 64 * 32 * 128 * 8;   // 2097152 16B-dst-chunks
constexpr int BCH = 32 * 32 * 128 * 8;   // 1048576
constexpr int TOTAL_CH = ACH + BCH;      // 3145728

__global__ void __launch_bounds__(256) convert_kernel(Params p)
{
    const int idx = blockIdx.x * 256 + threadIdx.x;
    if (idx >= TOTAL_CH) return;

    const float* src;
    __half* dst;
    if (idx < ACH) {
        const int c16 = idx & 7;
        const int r   = (idx >> 3) & 127;
        const int kc  = (idx >> 10) & 31;
        const int bt  = idx >> 15;
        src = (kc < 16 ? p.x : p.h)
              + (size_t)(bt * 128 + r) * 1024 + (kc & 15) * 64 + c16 * 8;
        dst = g_sA + ((size_t)(bt * 32 + kc) * 128 + r) * 64 + ((c16 ^ (r & 7)) * 8);
    } else {
        const int t   = idx - ACH;
        const int c16 = t & 7;
        const int r   = (t >> 3) & 127;        // g*32 + jl
        const int kc  = (t >> 10) & 31;
        const int jt  = t >> 15;
        const int g   = r >> 5, jl = r & 31;
        src = (kc < 16 ? p.W[g] : p.U[g])
              + (size_t)(jt * 32 + jl) * 1024 + (kc & 15) * 64 + c16 * 8;
        dst = g_sB + ((size_t)(jt * 32 + kc) * 128 + r) * 64 + ((c16 ^ (r & 7)) * 8);
    }
    const float4 v0 = *(const float4*)(src);
    const float4 v1 = *(const float4*)(src + 4);
    __half2 h0 = __floats2half2_rn(v0.x, v0.y);
    __half2 h1 = __floats2half2_rn(v0.z, v0.w);
    __half2 h2 = __floats2half2_rn(v1.x, v1.y);
    __half2 h3 = __floats2half2_rn(v1.z, v1.w);
    uint4 pk;
    pk.x = *(const uint32_t*)&h0;
    pk.y = *(const uint32_t*)&h1;
    pk.z = *(const uint32_t*)&h2;
    pk.w = *(const uint32_t*)&h3;
    *(uint4*)dst = pk;
}

// ---------------- pass 2: fp16 GEMM + fused LSTM epilogue ----------------
__global__ void __launch_bounds__(THREADS, 2)
lstm_mma_f16_kernel(Params p)
{
    extern __shared__ __align__(128) char smem[];
    const uint32_t sbase = smem_u32(smem);

    const int tid  = threadIdx.x;
    const int wid  = tid >> 5;
    const int lane = tid & 31;
    const int wm   = wid >> 1;        // 0..3 : rows wm*32
    const int wn   = wid & 1;         // 0..1 : j cols wn*16 per gate
    const int g4   = lane >> 2;
    const int t4   = lane & 3;

    const int bm = blockIdx.y * BM;
    const int j0 = blockIdx.x * BNG;

    const __half* tileA = g_sA + (size_t)blockIdx.y * (32u * 8192u);
    const __half* tileB = g_sB + (size_t)blockIdx.x * (32u * 8192u);

    const uint32_t mb = sbase + MBAR_OFF;
    auto FULL = [&](int s) { return mb + (uint32_t)s * 8u; };
    auto FREE = [&](int s) { return mb + 24u + (uint32_t)s * 8u; };

    if (tid == 0) {
        #pragma unroll
        for (int s = 0; s < 3; s++) { mbar_init(FULL(s), 1); mbar_init(FREE(s), 8); }
    }
    __syncthreads();

    // ---- prologue: stage chunks 0,1,2 ----
    if (tid == 0) {
        #pragma unroll
        for (int s = 0; s < 3; s++) {
            mbar_expect_tx(FULL(s), STAGE_BYTES);
            bulk_g2s(sbase + s * STAGE_BYTES,                 tileA + s * 8192, A_STAGE_BYTES, FULL(s));
            bulk_g2s(sbase + s * STAGE_BYTES + A_STAGE_BYTES, tileB + s * 8192, B_STAGE_BYTES, FULL(s));
        }
    }

    // ---- accumulators ----
    float acc[2][4][2][4];
    #pragma unroll
    for (int a = 0; a < 2; a++)
        #pragma unroll
        for (int b = 0; b < 4; b++)
            #pragma unroll
            for (int s = 0; s < 2; s++)
                #pragma unroll
                for (int q = 0; q < 4; q++) acc[a][b][s][q] = 0.0f;

    // ---- per-lane ldmatrix row/col selection ----
    const int a_rsel = (lane & 7) + (((lane >> 3) & 1) << 3);
    const int a_ckad = (lane >> 4);
    const int b_rsel = (lane & 7) + ((lane >> 4) << 3);
    const int b_ckad = ((lane >> 3) & 1);

    uint32_t a_base[2]; int a_rx[2];
    #pragma unroll
    for (int mt = 0; mt < 2; mt++) {
        const int row = wm * 32 + mt * 16 + a_rsel;
        a_base[mt] = sbase + (uint32_t)(row * 128);
        a_rx[mt]   = row & 7;
    }
    uint32_t b_base[4]; int b_rx[4];
    #pragma unroll
    for (int g = 0; g < 4; g++) {
        const int row = g * 32 + wn * 16 + b_rsel;
        b_base[g] = sbase + (uint32_t)(A_STAGE_BYTES + row * 128);
        b_rx[g]   = row & 7;
    }

    // one pipeline step: chunk kt lives in buffer S; use index = kt/3
    auto body = [&](auto Sc, int kt, int use) {
        constexpr int S = decltype(Sc)::value;
        constexpr uint32_t soff = (uint32_t)S * STAGE_BYTES;
        const uint32_t parity = (uint32_t)(use & 1);

        mbar_wait(FULL(S), parity);

        #pragma unroll
        for (int kk = 0; kk < 4; kk++) {
            uint32_t afr[2][4];
            #pragma unroll
            for (int mt = 0; mt < 2; mt++) {
                const int ck = kk * 2 + a_ckad;
                ldsm_x4(afr[mt], a_base[mt] + soff + ((ck ^ a_rx[mt]) << 4));
            }
            uint32_t bfr[4][4];
            #pragma unroll
            for (int g = 0; g < 4; g++) {
                const int ck = kk * 2 + b_ckad;
                ldsm_x4(bfr[g], b_base[g] + soff + ((ck ^ b_rx[g]) << 4));
            }
            #pragma unroll
            for (int mt = 0; mt < 2; mt++)
                #pragma unroll
                for (int g = 0; g < 4; g++) {
                    mma_f16(acc[mt][g][0], afr[mt], &bfr[g][0]);
                    mma_f16(acc[mt][g][1], afr[mt], &bfr[g][2]);
                }
        }

        if (lane == 0) {
            mbar_arrive(FREE(S));
            if (wid == 0) {
                const int kn = kt + 3;
                if (kn < KITERS) {
                    // wait until ALL warps finished reading buffer S this use
                    mbar_wait(FREE(S), parity);
                    mbar_expect_tx(FULL(S), STAGE_BYTES);
                    bulk_g2s(sbase + soff,                 tileA + kn * 8192, A_STAGE_BYTES, FULL(S));
                    bulk_g2s(sbase + soff + A_STAGE_BYTES, tileB + kn * 8192, B_STAGE_BYTES, FULL(S));
                }
            }
        }
    };

    // ---- main loop: 32 chunks = 10 x 3 + 2 ----
    for (int use = 0; use < 10; use++) {
        body(IC<0>{}, use * 3 + 0, use);
        body(IC<1>{}, use * 3 + 1, use);
        body(IC<2>{}, use * 3 + 2, use);
    }
    body(IC<0>{}, 30, 10);
    body(IC<1>{}, 31, 10);

    // ---- fused epilogue (register-resident) ----
    {
        float2 bb[4][2];
        #pragma unroll
        for (int g = 0; g < 4; g++)
            #pragma unroll
            for (int s2 = 0; s2 < 2; s2++)
                bb[g][s2] = *(const float2*)(p.bias[g] + j0 + wn * 16 + s2 * 8 + 2 * t4);

        #pragma unroll
        for (int mt = 0; mt < 2; mt++) {
            #pragma unroll
            for (int hh = 0; hh < 2; hh++) {
                const int row = bm + wm * 32 + mt * 16 + g4 + hh * 8;
                const size_t ro = (size_t)row * 1024 + j0 + wn * 16;
                #pragma unroll
                for (int s2 = 0; s2 < 2; s2++) {
                    const int co = s2 * 8 + 2 * t4;
                    const float2 cv = *(const float2*)(p.c + ro + co);
                    const int q = hh * 2;

                    const float i0 = sigm(acc[mt][0][s2][q]     + bb[0][s2].x);
                    const float i1 = sigm(acc[mt][0][s2][q + 1] + bb[0][s2].y);
                    const float f0 = sigm(acc[mt][1][s2][q]     + bb[1][s2].x);
                    const float f1 = sigm(acc[mt][1][s2][q + 1] + bb[1][s2].y);
                    const float o0 = sigm(acc[mt][2][s2][q]     + bb[2][s2].x);
                    const float o1 = sigm(acc[mt][2][s2][q + 1] + bb[2][s2].y);
                    const float c0 = ftanh(acc[mt][3][s2][q]     + bb[3][s2].x);
                    const float c1 = ftanh(acc[mt][3][s2][q + 1] + bb[3][s2].y);

                    const float nc0 = f0 * cv.x + i0 * c0;
                    const float nc1 = f1 * cv.y + i1 * c1;
                    float2 oh, oc;
                    oc.x = nc0; oc.y = nc1;
                    oh.x = o0 * ftanh(nc0);
                    oh.y = o1 * ftanh(nc1);
                    *(float2*)(p.outh + ro + co) = oh;
                    *(float2*)(p.outc + ro + co) = oc;
                }
            }
        }
    }
}

// ---------------- launch ----------------
extern "C" void kernel_launch(void* const* d_in, const int* in_sizes, int n_in,
                              void* d_out, int out_size)
{
    (void)in_sizes; (void)n_in; (void)out_size;

    Params p;
    p.x = (const float*)d_in[0];
    p.h = (const float*)d_in[1];
    p.c = (const float*)d_in[2];
    for (int g = 0; g < 4; g++) {   // (Wi,bi,Ui),(Wf,bf,Uf),(Wo,bo,Uo),(Wc,bc,Uc)
        p.W[g]    = (const float*)d_in[3 + 3 * g];
        p.bias[g] = (const float*)d_in[4 + 3 * g];
        p.U[g]    = (const float*)d_in[5 + 3 * g];
    }
    float* out = (float*)d_out;
    p.outh = out;
    p.outc = out + (size_t)BATCH * DH;

    static bool configured = false;
    if (!configured) {
        cudaFuncSetAttribute(lstm_mma_f16_kernel,
                             cudaFuncAttributeMaxDynamicSharedMemorySize, SMEM_BYTES);
        configured = true;
    }

    convert_kernel<<<(TOTAL_CH + 255) / 256, 256>>>(p);

    dim3 grid(DH / BNG, BATCH / BM);   // (32, 64)
    lstm_mma_f16_kernel<<<grid, THREADS, SMEM_BYTES>>>(p);
}